// round 8
// baseline (speedup 1.0000x reference)
#include <cuda_runtime.h>
#include <cuda_fp16.h>
#include <math.h>

#define BB 512
#define TT 512

// ---------------- device scratch (allocation-free rule) ----------------
__device__ __half g_gxh[(size_t)TT * BB * 512];   // gate pre-activations (fp16)
__device__ float  g_h1[(size_t)BB * TT * 32];     // layer1 output
__device__ float  g_h2[(size_t)BB * TT * 48];     // layer2 output
__device__ float  g_Wt3[128 * 512];               // Whh3 transposed [k][col]

// ---------------- f32x2 helpers ----------------
__device__ __forceinline__ unsigned long long pk2(float a, float b) {
    unsigned long long r;
    asm("mov.b64 %0, {%1,%2};" : "=l"(r) : "f"(a), "f"(b));
    return r;
}
__device__ __forceinline__ void upk2(unsigned long long v, float& a, float& b) {
    asm("mov.b64 {%0,%1}, %2;" : "=f"(a), "=f"(b) : "l"(v));
}
__device__ __forceinline__ void fma2_(unsigned long long& d, unsigned long long a,
                                      unsigned long long b) {
    asm("fma.rn.f32x2 %0, %1, %2, %0;" : "+l"(d) : "l"(a), "l"(b));
}
__device__ __forceinline__ unsigned long long add2_(unsigned long long a,
                                                    unsigned long long b) {
    unsigned long long r;
    asm("add.rn.f32x2 %0, %1, %2;" : "=l"(r) : "l"(a), "l"(b));
    return r;
}
__device__ __forceinline__ float sig_(float x) { return 1.0f / (1.0f + __expf(-x)); }
__device__ __forceinline__ float th_(float x) { return 1.0f - 2.0f / (__expf(2.0f * x) + 1.0f); }

// ---------------------------------------------------------------------------
// Input projection (R4-proven): 1 col/thread, f32x2 row-pair accumulation.
// ---------------------------------------------------------------------------
template <int D, int NT, int NTOT, int MT>
__global__ void __launch_bounds__(NT)
lstm_projH(const float* __restrict__ x, const float* __restrict__ Wih,
           const float* __restrict__ bih, const float* __restrict__ bhh,
           __half* __restrict__ gx)
{
    const int tid = threadIdx.x;
    const int col = blockIdx.y * NT + tid;

    unsigned long long w2[D];
#pragma unroll
    for (int k = 0; k < D; k++) {
        float w = __ldg(&Wih[col * D + k]);
        w2[k] = pk2(w, w);
    }
    const float bsum = __ldg(&bih[col]) + __ldg(&bhh[col]);
    const unsigned long long b2 = pk2(bsum, bsum);

    __shared__ float4 xs[MT][D / 4];
    const int ntiles = (BB * TT) / MT;

    for (int tile = blockIdx.x; tile < ntiles; tile += gridDim.x) {
        __syncthreads();
        for (int i = tid; i < MT * D / 4; i += NT)
            ((float4*)xs)[i] = ((const float4*)x)[(size_t)tile * (MT * D / 4) + i];
        __syncthreads();

#pragma unroll 2
        for (int r = 0; r < MT; r += 2) {
            unsigned long long a0 = b2, a1 = 0ull, a2 = 0ull, a3 = 0ull;
#pragma unroll
            for (int k4 = 0; k4 < D / 4; k4++) {
                float4 v0 = xs[r][k4];
                float4 v1 = xs[r + 1][k4];
                fma2_(a0, w2[4 * k4 + 0], pk2(v0.x, v1.x));
                fma2_(a1, w2[4 * k4 + 1], pk2(v0.y, v1.y));
                fma2_(a2, w2[4 * k4 + 2], pk2(v0.z, v1.z));
                fma2_(a3, w2[4 * k4 + 3], pk2(v0.w, v1.w));
            }
            unsigned long long s = add2_(add2_(a0, a1), add2_(a2, a3));
            float g0, g1;
            upk2(s, g0, g1);
            int m = tile * MT + r;
            int b = m >> 9, t = m & 511;
            gx[((size_t)t * BB + b) * NTOT + col]       = __float2half(g0);
            gx[((size_t)(t + 1) * BB + b) * NTOT + col] = __float2half(g1);
        }
    }
}

// ---------------------------------------------------------------------------
// Small-layer recurrence (R4-proven), fp16 gx, depth-2 prefetch.
// ---------------------------------------------------------------------------
template <int H>
__global__ void __launch_bounds__(4 * H)
lstm_recur_small(const __half* __restrict__ gx,  // [T][B][4H] fp16
                 const float* __restrict__ Whh,  // [4H][H]
                 float* __restrict__ out)        // [B][T][H]
{
    constexpr int G = 4 * H;
    const int col = threadIdx.x;
    const int b0 = blockIdx.x * 2;

    unsigned long long wh2[H];
#pragma unroll
    for (int k = 0; k < H; k++) {
        float w = __ldg(&Whh[col * H + k]);
        wh2[k] = pk2(w, w);
    }

    __shared__ unsigned long long h2[H];
    __shared__ unsigned long long g2[G];
    if (col < H) h2[col] = 0ull;

    const int erow = col & 1, ecol = col >> 1;
    float c = 0.f;

    const __half* gbase = gx + (size_t)b0 * G + col;
    const size_t tstride = (size_t)BB * G;

    __half A0 = gbase[0], A1 = gbase[G];
    __half B0 = gbase[tstride], B1 = gbase[tstride + G];
    __syncthreads();

    for (int t = 0; t < TT; t++) {
        __half C0 = __float2half(0.f), C1 = C0;
        if (t + 2 < TT) {
            const __half* gp = gbase + (size_t)(t + 2) * tstride;
            C0 = gp[0]; C1 = gp[G];
        }
        unsigned long long a0 = 0ull, a1 = 0ull, a2 = 0ull, a3 = 0ull;
#pragma unroll
        for (int k = 0; k < H; k += 4) {
            fma2_(a0, wh2[k + 0], h2[k + 0]);
            fma2_(a1, wh2[k + 1], h2[k + 1]);
            fma2_(a2, wh2[k + 2], h2[k + 2]);
            fma2_(a3, wh2[k + 3], h2[k + 3]);
        }
        g2[col] = add2_(add2_(add2_(a0, a1), add2_(a2, a3)),
                        pk2(__half2float(A0), __half2float(A1)));
        A0 = B0; A1 = B1; B0 = C0; B1 = C1;
        __syncthreads();

        if (col < 2 * H) {
            const float* gf = (const float*)g2;
            float gi = gf[2 * ecol + erow];
            float gF = gf[2 * (H + ecol) + erow];
            float gg = gf[2 * (2 * H + ecol) + erow];
            float go = gf[2 * (3 * H + ecol) + erow];
            c = sig_(gF) * c + sig_(gi) * th_(gg);
            float h = sig_(go) * th_(c);
            ((float*)h2)[2 * ecol + erow] = h;
            out[((size_t)(b0 + erow) * TT + t) * H + ecol] = h;
        }
        __syncthreads();
    }
}

// ---------------------------------------------------------------------------
// Layer-3 recurrence via warp mma.sync m16n8k16 (fp16 in, fp32 accum).
// 32 blocks x 256 threads (8 warps). Block owns 16 batch rows; warp w owns
// h-cols [16w,16w+16) -> 8 gate n-tiles {i0,i1,f0,f1,g0,g1,o0,o1}.
// Whh3 resident as B-fragments in registers (zero weight traffic in loop).
// Epilogue fully in-register; double-buffered fp16 h in smem; 1 sync/step.
// ---------------------------------------------------------------------------
__device__ __forceinline__ unsigned smem_u32(const void* p) {
    return (unsigned)__cvta_generic_to_shared(p);
}
__device__ __forceinline__ void ldmx4(unsigned& a0, unsigned& a1, unsigned& a2,
                                      unsigned& a3, unsigned addr) {
    asm volatile("ldmatrix.sync.aligned.m8n8.x4.shared.b16 {%0,%1,%2,%3}, [%4];"
                 : "=r"(a0), "=r"(a1), "=r"(a2), "=r"(a3) : "r"(addr));
}
__device__ __forceinline__ void mma16816(float* d, unsigned a0, unsigned a1,
                                         unsigned a2, unsigned a3,
                                         unsigned b0, unsigned b1) {
    asm volatile(
        "mma.sync.aligned.m16n8k16.row.col.f32.f16.f16.f32 "
        "{%0,%1,%2,%3}, {%4,%5,%6,%7}, {%8,%9}, {%0,%1,%2,%3};"
        : "+f"(d[0]), "+f"(d[1]), "+f"(d[2]), "+f"(d[3])
        : "r"(a0), "r"(a1), "r"(a2), "r"(a3), "r"(b0), "r"(b1));
}

#define HPAD 136   // h smem row stride in halves (272B -> conflict-free ldmatrix)

__global__ void __launch_bounds__(256, 1)
lstm_recur_mma(const __half* __restrict__ gx,  // [T][B][512] fp16
               const float* __restrict__ Wt,   // [128][512] Whh3 transposed
               float* __restrict__ out,        // [B][T][128]
               float* __restrict__ hn)         // [B][128]
{
    __shared__ __align__(16) __half hsm[2][16][HPAD];

    const int tid = threadIdx.x;
    const int w = tid >> 5, l = tid & 31;
    const int l4 = l & 3, lq = l >> 2;
    const int b0 = blockIdx.x * 16;

    // ---- B fragments: Whh3 fully register-resident ----
    unsigned bf[8][8][2];
#pragma unroll
    for (int kt = 0; kt < 8; kt++)
#pragma unroll
        for (int ti = 0; ti < 8; ti++) {
            int n = 128 * (ti >> 1) + 16 * w + 8 * (ti & 1) + lq;
            int k0 = 16 * kt + 2 * l4;
            __half2 v0 = __floats2half2_rn(__ldg(&Wt[k0 * 512 + n]),
                                           __ldg(&Wt[(k0 + 1) * 512 + n]));
            __half2 v1 = __floats2half2_rn(__ldg(&Wt[(k0 + 8) * 512 + n]),
                                           __ldg(&Wt[(k0 + 9) * 512 + n]));
            bf[kt][ti][0] = *(unsigned*)&v0;
            bf[kt][ti][1] = *(unsigned*)&v1;
        }

    // zero the h buffer read at t=0 (buffer 1)
    for (int i = tid; i < 16 * HPAD; i += 256) ((__half*)hsm[1])[i] = __float2half(0.f);

    float c[8];
#pragma unroll
    for (int i = 0; i < 8; i++) c[i] = 0.f;

    // ldmatrix A address pieces: row = l&15, col-group = (l>>4)*8
    const int arow = l & 15, acg = (l >> 4) * 8;

    __syncthreads();

    for (int t = 0; t < TT; t++) {
        const int rb = (t + 1) & 1;   // read h written at t-1

        // prefetch gx fragments (16 half2) — latency hidden by mma loop
        unsigned gxf[16];
        const __half* gb = gx + ((size_t)t * BB + b0) * 512;
#pragma unroll
        for (int ti = 0; ti < 8; ti++) {
            int colb = 128 * (ti >> 1) + 16 * w + 8 * (ti & 1) + 2 * l4;
#pragma unroll
            for (int rr = 0; rr < 2; rr++)
                gxf[ti * 2 + rr] =
                    *(const unsigned*)(gb + (size_t)(lq + 8 * rr) * 512 + colb);
        }

        float d[8][4];
#pragma unroll
        for (int ti = 0; ti < 8; ti++)
#pragma unroll
            for (int r = 0; r < 4; r++) d[ti][r] = 0.f;

#pragma unroll
        for (int kt = 0; kt < 8; kt++) {
            unsigned a0, a1, a2, a3;
            unsigned addr = smem_u32(&hsm[rb][arow][acg + 16 * kt]);
            ldmx4(a0, a1, a2, a3, addr);
#pragma unroll
            for (int ti = 0; ti < 8; ti++)
                mma16816(d[ti], a0, a1, a2, a3, bf[kt][ti][0], bf[kt][ti][1]);
        }

        // add gx
#pragma unroll
        for (int ti = 0; ti < 8; ti++)
#pragma unroll
            for (int rr = 0; rr < 2; rr++) {
                float2 f = __half22float2(*(__half2*)&gxf[ti * 2 + rr]);
                d[ti][2 * rr + 0] += f.x;
                d[ti][2 * rr + 1] += f.y;
            }

        // epilogue (in-register: i,f,g,o share lane layout)
#pragma unroll
        for (int tp = 0; tp < 2; tp++)
#pragma unroll
            for (int rr = 0; rr < 2; rr++)
#pragma unroll
                for (int cc = 0; cc < 2; cc++) {
                    int reg = 2 * rr + cc, ci = tp * 4 + reg;
                    float gi = d[0 + tp][reg];
                    float gF = d[2 + tp][reg];
                    float gg = d[4 + tp][reg];
                    float go = d[6 + tp][reg];
                    c[ci] = sig_(gF) * c[ci] + sig_(gi) * th_(gg);
                    float h = sig_(go) * th_(c[ci]);
                    int hc = 16 * w + 8 * tp + 2 * l4 + cc;
                    int r = lq + 8 * rr;
                    hsm[t & 1][r][hc] = __float2half(h);
                    out[((size_t)(b0 + r) * TT + t) * 128 + hc] = h;
                    if (t == TT - 1) hn[(size_t)(b0 + r) * 128 + hc] = h;
                }
        __syncthreads();
    }
}

// ---------------------------------------------------------------------------
__global__ void transposeW3(const float* __restrict__ Whh, float* __restrict__ Wt)
{
    int i = blockIdx.x * 256 + threadIdx.x;
    if (i < 128 * 512) {
        int k = i >> 9, col = i & 511;
        Wt[i] = Whh[col * 128 + k];
    }
}

// ---------------------------------------------------------------------------
extern "C" void kernel_launch(void* const* d_in, const int* in_sizes, int n_in,
                              void* d_out, int out_size)
{
    const float* z    = (const float*)d_in[0];
    const float* Wih1 = (const float*)d_in[1];
    const float* Whh1 = (const float*)d_in[2];
    const float* bih1 = (const float*)d_in[3];
    const float* bhh1 = (const float*)d_in[4];
    const float* Wih2 = (const float*)d_in[5];
    const float* Whh2 = (const float*)d_in[6];
    const float* bih2 = (const float*)d_in[7];
    const float* bhh2 = (const float*)d_in[8];
    const float* Wih3 = (const float*)d_in[9];
    const float* Whh3 = (const float*)d_in[10];
    const float* bih3 = (const float*)d_in[11];
    const float* bhh3 = (const float*)d_in[12];

    float* dec = (float*)d_out;                        // [B,T,128]
    float* hn  = dec + (size_t)BB * TT * 128;          // [1,B,128]

    __half* gx;
    float *h1, *h2, *Wt3;
    cudaGetSymbolAddress((void**)&gx, g_gxh);
    cudaGetSymbolAddress((void**)&h1, g_h1);
    cudaGetSymbolAddress((void**)&h2, g_h2);
    cudaGetSymbolAddress((void**)&Wt3, g_Wt3);

    transposeW3<<<256, 256>>>(Whh3, Wt3);

    // Layer 1: 64 -> 32
    lstm_projH<64, 128, 128, 64><<<dim3(2048, 1), 128>>>(z, Wih1, bih1, bhh1, gx);
    lstm_recur_small<32><<<BB / 2, 128>>>(gx, Whh1, h1);

    // Layer 2: 32 -> 48
    lstm_projH<32, 192, 192, 64><<<dim3(2048, 1), 192>>>(h1, Wih2, bih2, bhh2, gx);
    lstm_recur_small<48><<<BB / 2, 192>>>(gx, Whh2, h2);

    // Layer 3: 48 -> 128
    lstm_projH<48, 256, 512, 64><<<dim3(2048, 2), 256>>>(h2, Wih3, bih3, bhh3, gx);
    lstm_recur_mma<<<32, 256>>>(gx, Wt3, dec, hn);
}